// round 13
// baseline (speedup 1.0000x reference)
#include <cuda_runtime.h>
#include <cuda_fp16.h>
#include <math.h>
#include <stdint.h>

#define BATCH 64
#define S 512
#define D 768
#define W 256
#define KX 1536     // 2*D router input
#define H 256       // router hidden (= GEMM N)
#define L 7
#define ROWS (BATCH * W)   // 16384
#define CTA_M 64
#define KT2 64             // K-tile (fp16 elems) = 128 bytes = one SW128 row
#define NITER (KX / KT2)   // 24
#define NSTAGE 3

// stage = B tile only (A comes via LDG): 256 rows x 128B
#define STAGE_BYTES 32768u
#define OFF_TILES 4096u
#define SMEM_TOTAL (OFF_TILES + NSTAGE * STAGE_BYTES)   // 102400 -> 2 CTAs/SM

// fp16 operands (single rounding)
__device__ __align__(16) __half g_xh[(size_t)ROWS * KX];
__device__ __align__(16) __half g_w1[(size_t)H * KX];   // [n][k]

__device__ __forceinline__ uint32_t smem_u32(const void* p) {
    uint32_t a;
    asm("{ .reg .u64 t; cvta.to.shared.u64 t, %1; cvt.u32.u64 %0, t; }"
        : "=r"(a) : "l"(p));
    return a;
}
#define SWZ(x) ((x) ^ (((x) >> 3) & 0x70))
__device__ __forceinline__ void cp16(uint32_t dst, const void* src) {
    asm volatile("cp.async.cg.shared.global [%0], [%1], 16;" :: "r"(dst), "l"(src));
}
#define CP_COMMIT() asm volatile("cp.async.commit_group;" ::: "memory")

#define LDSM_X4(R, A)                                                        \
    asm volatile("ldmatrix.sync.aligned.m8n8.x4.shared.b16 {%0,%1,%2,%3}, [%4];" \
        : "=r"((R)[0]), "=r"((R)[1]), "=r"((R)[2]), "=r"((R)[3]) : "r"(A))

#define MMA_F16(Dd, Aa, Bb)                                                  \
    asm volatile("mma.sync.aligned.m16n8k16.row.col.f32.f16.f16.f32 "        \
        "{%0,%1,%2,%3}, {%4,%5,%6,%7}, {%8,%9}, {%0,%1,%2,%3};"              \
        : "+f"((Dd)[0]), "+f"((Dd)[1]), "+f"((Dd)[2]), "+f"((Dd)[3])         \
        : "r"((Aa)[0]), "r"((Aa)[1]), "r"((Aa)[2]), "r"((Aa)[3]),            \
          "r"((Bb)[0]), "r"((Bb)[1]))

// ---------------------------------------------------------------------------
// Align + prep in ONE grid (unchanged from R11, measured ~55us)
// ---------------------------------------------------------------------------
__global__ __launch_bounds__(256) void align_kernel(
    const float* __restrict__ hing, const float* __restrict__ rob,
    const int* __restrict__ hids, const int* __restrict__ rids,
    const float* __restrict__ w1)
{
    int tid = threadIdx.x;
    int bid = blockIdx.x;

    if (bid >= (ROWS * 2) / 8) {                    // prep_w1 blocks
        int idx = (bid - (ROWS * 2) / 8) * 256 + tid;   // n*KX + k
        int n = idx / KX;
        int k = idx - n * KX;
        g_w1[idx] = __float2half_rn(w1[(size_t)k * H + n]);
        return;
    }

    int unit = bid * 8 + (tid >> 5);   // 0 .. ROWS*2-1
    int lane = tid & 31;
    int srci = unit & 1;
    int row  = unit >> 1;
    int b = row >> 8;
    int w = row & (W - 1);

    const int* ids = (srci ? rids : hids) + b * S;
    const float* src = srci ? rob : hing;

    // interleaved lower_bound(w) / lower_bound(w+1), 10 steps
    int lo = 0, h = S, hi = 0, g = S;
    #pragma unroll 1
    for (int i = 0; i < 10; i++) {
        int m = (lo + h) >> 1;
        int n = (hi + g) >> 1;
        int a = ids[m < S ? m : S - 1];
        int c = ids[n < S ? n : S - 1];
        if (lo < h) { if (a < w)  lo = m + 1; else h = m; }
        if (hi < g) { if (c <= w) hi = n + 1; else g = n; }
    }

    float inv = (hi > lo) ? 1.0f / (float)(hi - lo) : 0.0f;
    const float4* base = (const float4*)(src + (size_t)b * S * D);
    __half2* dh = (__half2*)(g_xh + (size_t)row * KX + srci * D);

    float4 acc[6];
    #pragma unroll
    for (int t = 0; t < 6; t++) acc[t] = make_float4(0.f, 0.f, 0.f, 0.f);
    #pragma unroll 1
    for (int s = lo; s < hi; s++) {
        const float4* rowp = base + (size_t)s * (D / 4) + lane;
        #pragma unroll
        for (int t = 0; t < 6; t++) {
            float4 v = rowp[32 * t];
            acc[t].x += v.x; acc[t].y += v.y; acc[t].z += v.z; acc[t].w += v.w;
        }
    }
    #pragma unroll
    for (int t = 0; t < 6; t++) {
        int c4 = (lane + 32 * t) * 2;   // half2 index within D
        __half2 p0, p1;
        p0.x = __float2half_rn(acc[t].x * inv);
        p0.y = __float2half_rn(acc[t].y * inv);
        p1.x = __float2half_rn(acc[t].z * inv);
        p1.y = __float2half_rn(acc[t].w * inv);
        dh[c4]     = p0;
        dh[c4 + 1] = p1;
    }
}

// ---------------------------------------------------------------------------
// Router: mma.sync fp16 GEMM, CTA M=64 N=256 K=1536; B via 3-stage cp.async
// (single sync/iter, prefetch distance 2); A fragments via LDG.32 straight
// from g_xh (L1/L2-resident), no A smem path. 2 CTAs/SM.
// + fused alpha / blend / head / l2 epilogue.
// ---------------------------------------------------------------------------
__device__ __forceinline__ void load_B(uint32_t st, int kk, int tid)
{
    const __half* bw = g_w1 + kk;
    #pragma unroll
    for (int t = 0; t < 8; t++) {
        int idx = t * 256 + tid;           // 2048 chunks: 256 rows x 8
        int n = idx >> 3, c = idx & 7;
        uint32_t sw = SWZ((uint32_t)(n * 128 + c * 16));
        cp16(st + sw, bw + (size_t)n * KX + c * 8);
    }
}

__global__ __launch_bounds__(256, 2) void router_kernel(
    const float* __restrict__ b1, const float* __restrict__ w2,
    const float* __restrict__ b2p,
    const float* __restrict__ headw, const float* __restrict__ headb,
    float* __restrict__ out)
{
    extern __shared__ char smem[];
    uint32_t sb = smem_u32(smem);
    int tid = threadIdx.x;
    int wid = tid >> 5, lane = tid & 31;
    int warp_m = wid >> 2;        // 0..1  (rows warp_m*32 .. +32)
    int warp_n = wid & 3;         // 0..3  (cols warp_n*64 .. +64)
    int r0 = blockIdx.x * CTA_M;

    float* s_b1    = (float*)(smem);
    float* s_w2    = (float*)(smem + 1024);
    float* s_part  = (float*)(smem + 2048);   // 64 floats
    float* s_alpha = (float*)(smem + 2304);   // 64 floats

    s_b1[tid] = b1[tid];
    s_w2[tid] = w2[tid];
    if (tid < CTA_M) s_part[tid] = 0.0f;
    float b2 = *b2p;

    // prologue: stages 0 and 1
    load_B(sb + OFF_TILES, 0, tid);
    CP_COMMIT();
    load_B(sb + OFF_TILES + STAGE_BYTES, KT2, tid);
    CP_COMMIT();

    float acc[2][8][4];
    #pragma unroll
    for (int mi = 0; mi < 2; mi++)
        #pragma unroll
        for (int ni = 0; ni < 8; ni++)
            #pragma unroll
            for (int j = 0; j < 4; j++) acc[mi][ni][j] = 0.0f;

    // A fragment gmem base: row = r0 + warp_m*32 + (lane>>2), k = (lane&3)*2
    const __half* aBase = g_xh +
        (size_t)(r0 + warp_m * 32 + (lane >> 2)) * KX + (lane & 3) * 2;

    // B ldsm addressing (R11-validated)
    int nrow  = warp_n * 64 + (((lane >> 4) & 1) << 3) + (lane & 7);
    uint32_t bcol = (((uint32_t)(lane >> 3)) & 1) << 4;
    uint32_t offB[4];
    #pragma unroll
    for (int g = 0; g < 4; g++)
        offB[g] = SWZ((uint32_t)((nrow + g * 16) * 128) + bcol);

    int stage = 0;
    for (int it = 0; it < NITER; it++) {
        if (it + 1 < NITER)
            asm volatile("cp.async.wait_group 1;" ::: "memory");
        else
            asm volatile("cp.async.wait_group 0;" ::: "memory");
        __syncthreads();   // publish stage it; all warps done with stage it-1

        if (it + 2 < NITER) {
            int s2 = stage + 2; if (s2 >= NSTAGE) s2 -= NSTAGE;
            load_B(sb + OFF_TILES + (uint32_t)s2 * STAGE_BYTES,
                   (it + 2) * KT2, tid);
            CP_COMMIT();
        }

        // A fragments for this k-tile via LDG (32 regs)
        uint32_t aa[2][4][4];
        const __half* ap = aBase + it * KT2;
        #pragma unroll
        for (int mi = 0; mi < 2; mi++) {
            const __half* am = ap + mi * 16 * KX;
            #pragma unroll
            for (int ks = 0; ks < 4; ks++) {
                const __half* p = am + ks * 16;
                aa[mi][ks][0] = *(const uint32_t*)(p);
                aa[mi][ks][1] = *(const uint32_t*)(p + 8 * KX);
                aa[mi][ks][2] = *(const uint32_t*)(p + 8);
                aa[mi][ks][3] = *(const uint32_t*)(p + 8 * KX + 8);
            }
        }

        uint32_t st = sb + OFF_TILES + (uint32_t)stage * STAGE_BYTES;
        #pragma unroll
        for (int ks = 0; ks < 4; ks++) {
            uint32_t kb = (uint32_t)ks * 32;
            uint32_t bb[8][2];
            #pragma unroll
            for (int g = 0; g < 4; g++) {
                uint32_t rb[4];
                LDSM_X4(rb, st + (offB[g] ^ kb));
                bb[2 * g][0] = rb[0]; bb[2 * g][1] = rb[1];
                bb[2 * g + 1][0] = rb[2]; bb[2 * g + 1][1] = rb[3];
            }
            #pragma unroll
            for (int mi = 0; mi < 2; mi++)
                #pragma unroll
                for (int ni = 0; ni < 8; ni++)
                    MMA_F16(acc[mi][ni], aa[mi][ks], bb[ni]);
        }

        if (++stage == NSTAGE) stage = 0;
    }

    // alpha partials: relu(hdn + b1) . w2 over this warp's 64 columns
    #pragma unroll
    for (int mi = 0; mi < 2; mi++) {
        #pragma unroll
        for (int rh = 0; rh < 2; rh++) {
            float part = 0.0f;
            #pragma unroll
            for (int ni = 0; ni < 8; ni++) {
                int col0 = warp_n * 64 + ni * 8 + 2 * (lane & 3);
                float h0 = acc[mi][ni][rh * 2 + 0] + s_b1[col0];
                float h1 = acc[mi][ni][rh * 2 + 1] + s_b1[col0 + 1];
                h0 = h0 > 0.f ? h0 : 0.f;
                h1 = h1 > 0.f ? h1 : 0.f;
                part = fmaf(h0, s_w2[col0], part);
                part = fmaf(h1, s_w2[col0 + 1], part);
            }
            part += __shfl_xor_sync(0xffffffffu, part, 1);
            part += __shfl_xor_sync(0xffffffffu, part, 2);
            if ((lane & 3) == 0)
                atomicAdd(&s_part[warp_m * 32 + mi * 16 + rh * 8 + (lane >> 2)], part);
        }
    }
    __syncthreads();
    if (tid < CTA_M) {
        float z = s_part[tid] + b2;
        s_alpha[tid] = 1.0f / (1.0f + expf(-z));
    }
    __syncthreads();

    // blend/head/l2 epilogue: 8 warps x 8 words
    float* out_logits = out;
    float* out_alpha  = out + (size_t)ROWS * L;
    float* out_l2     = out_alpha + ROWS;

    #pragma unroll 1
    for (int wi = 0; wi < 8; wi++) {
        int li = wid * 8 + wi;
        size_t row = (size_t)(r0 + li);
        float al = s_alpha[li];
        float oma = 1.0f - al;
        const __half2* xh2 = (const __half2*)(g_xh + row * KX);

        float lg[L];
        #pragma unroll
        for (int l = 0; l < L; l++) lg[l] = 0.0f;
        float l2 = 0.0f;

        #pragma unroll 1
        for (int d2 = lane; d2 < D / 2; d2 += 32) {
            __half2 hh2 = xh2[d2];
            __half2 rr2 = xh2[D / 2 + d2];
            float hh[2], hr[2];
            hh[0] = __half2float(hh2.x); hh[1] = __half2float(hh2.y);
            hr[0] = __half2float(rr2.x); hr[1] = __half2float(rr2.y);
            #pragma unroll
            for (int u = 0; u < 2; u++) {
                int d = d2 * 2 + u;
                float bl = al * hh[u] + oma * hr[u];
                float df = hh[u] - hr[u];
                l2 = fmaf(df, df, l2);
                #pragma unroll
                for (int l = 0; l < L; l++)
                    lg[l] = fmaf(bl, headw[(size_t)d * L + l], lg[l]);
            }
        }
        #pragma unroll
        for (int o = 16; o > 0; o >>= 1) {
            #pragma unroll
            for (int l = 0; l < L; l++)
                lg[l] += __shfl_xor_sync(0xffffffffu, lg[l], o);
            l2 += __shfl_xor_sync(0xffffffffu, l2, o);
        }
        if (lane == 0) {
            #pragma unroll
            for (int l = 0; l < L; l++)
                out_logits[row * L + l] = lg[l] + headb[l];
            out_alpha[row] = al;
            out_l2[row] = sqrtf(l2);
        }
    }
}

extern "C" void kernel_launch(void* const* d_in, const int* in_sizes, int n_in,
                              void* d_out, int out_size)
{
    const float* hing = (const float*)d_in[0];
    const float* rob  = (const float*)d_in[1];
    const int*   hids = (const int*)d_in[2];
    const int*   rids = (const int*)d_in[3];
    // d_in[4] = num_words (unused by the reference outputs)
    const float* w1 = (const float*)d_in[5];
    const float* b1 = (const float*)d_in[6];
    const float* w2 = (const float*)d_in[7];
    const float* b2 = (const float*)d_in[8];
    const float* hw = (const float*)d_in[9];
    const float* hb = (const float*)d_in[10];
    float* out = (float*)d_out;

    cudaFuncSetAttribute(router_kernel,
                         cudaFuncAttributeMaxDynamicSharedMemorySize, SMEM_TOTAL);

    align_kernel<<<(ROWS * 2) / 8 + (KX * H) / 256, 256>>>(hing, rob, hids, rids, w1);
    router_kernel<<<ROWS / CTA_M, 256, SMEM_TOTAL>>>(b1, w2, b2, hw, hb, out);
}

// round 14
// speedup vs baseline: 1.3436x; 1.3436x over previous
#include <cuda_runtime.h>
#include <cuda_fp16.h>
#include <math.h>
#include <stdint.h>

#define BATCH 64
#define S 512
#define D 768
#define W 256
#define KX 1536     // 2*D router input
#define H 256       // router hidden (= GEMM N)
#define L 7
#define ROWS (BATCH * W)   // 16384
#define CTA_M 128
#define NT 512
#define KT2 64             // K-tile (fp16 elems) = 128 bytes = one SW128 row
#define NITER (KX / KT2)   // 24

// stage layout (bytes): A 16K | B 32K
#define OFF_A 0u
#define OFF_B 16384u
#define STAGE_BYTES 49152u
#define OFF_TILES 4096u
#define SMEM_TOTAL (OFF_TILES + 2 * STAGE_BYTES)   // 102400 -> 1 CTA/SM, 16 warps

// fp16 operands (single rounding)
__device__ __align__(16) __half g_xh[(size_t)ROWS * KX];
__device__ __align__(16) __half g_w1[(size_t)H * KX];   // [n][k]

__device__ __forceinline__ uint32_t smem_u32(const void* p) {
    uint32_t a;
    asm("{ .reg .u64 t; cvta.to.shared.u64 t, %1; cvt.u32.u64 %0, t; }"
        : "=r"(a) : "l"(p));
    return a;
}
#define SWZ(x) ((x) ^ (((x) >> 3) & 0x70))
__device__ __forceinline__ void cp16(uint32_t dst, const void* src) {
    asm volatile("cp.async.cg.shared.global [%0], [%1], 16;" :: "r"(dst), "l"(src));
}
#define CP_COMMIT() asm volatile("cp.async.commit_group;" ::: "memory")

#define LDSM_X4(R, A)                                                        \
    asm volatile("ldmatrix.sync.aligned.m8n8.x4.shared.b16 {%0,%1,%2,%3}, [%4];" \
        : "=r"((R)[0]), "=r"((R)[1]), "=r"((R)[2]), "=r"((R)[3]) : "r"(A))

#define MMA_F16(Dd, Aa, Bb)                                                  \
    asm volatile("mma.sync.aligned.m16n8k16.row.col.f32.f16.f16.f32 "        \
        "{%0,%1,%2,%3}, {%4,%5,%6,%7}, {%8,%9}, {%0,%1,%2,%3};"              \
        : "+f"((Dd)[0]), "+f"((Dd)[1]), "+f"((Dd)[2]), "+f"((Dd)[3])         \
        : "r"((Aa)[0]), "r"((Aa)[1]), "r"((Aa)[2]), "r"((Aa)[3]),            \
          "r"((Bb)[0]), "r"((Bb)[1]))

// ---------------------------------------------------------------------------
// Align + prep in ONE grid (R11 structure; stores vectorized to 8B)
// ---------------------------------------------------------------------------
__global__ __launch_bounds__(256) void align_kernel(
    const float* __restrict__ hing, const float* __restrict__ rob,
    const int* __restrict__ hids, const int* __restrict__ rids,
    const float* __restrict__ w1)
{
    int tid = threadIdx.x;
    int bid = blockIdx.x;

    if (bid >= (ROWS * 2) / 8) {                    // prep_w1 blocks
        int idx = (bid - (ROWS * 2) / 8) * 256 + tid;   // n*KX + k
        int n = idx / KX;
        int k = idx - n * KX;
        g_w1[idx] = __float2half_rn(w1[(size_t)k * H + n]);
        return;
    }

    int unit = bid * 8 + (tid >> 5);   // 0 .. ROWS*2-1
    int lane = tid & 31;
    int srci = unit & 1;
    int row  = unit >> 1;
    int b = row >> 8;
    int w = row & (W - 1);

    const int* ids = (srci ? rids : hids) + b * S;
    const float* src = srci ? rob : hing;

    // interleaved lower_bound(w) / lower_bound(w+1), 10 steps
    int lo = 0, h = S, hi = 0, g = S;
    #pragma unroll 1
    for (int i = 0; i < 10; i++) {
        int m = (lo + h) >> 1;
        int n = (hi + g) >> 1;
        int a = ids[m < S ? m : S - 1];
        int c = ids[n < S ? n : S - 1];
        if (lo < h) { if (a < w)  lo = m + 1; else h = m; }
        if (hi < g) { if (c <= w) hi = n + 1; else g = n; }
    }

    float inv = (hi > lo) ? 1.0f / (float)(hi - lo) : 0.0f;
    const float4* base = (const float4*)(src + (size_t)b * S * D);
    __half* dh = g_xh + (size_t)row * KX + srci * D;

    float4 acc[6];
    #pragma unroll
    for (int t = 0; t < 6; t++) acc[t] = make_float4(0.f, 0.f, 0.f, 0.f);
    #pragma unroll 1
    for (int s = lo; s < hi; s++) {
        const float4* rowp = base + (size_t)s * (D / 4) + lane;
        #pragma unroll
        for (int t = 0; t < 6; t++) {
            float4 v = rowp[32 * t];
            acc[t].x += v.x; acc[t].y += v.y; acc[t].z += v.z; acc[t].w += v.w;
        }
    }
    #pragma unroll
    for (int t = 0; t < 6; t++) {
        __half2 p0, p1;
        p0.x = __float2half_rn(acc[t].x * inv);
        p0.y = __float2half_rn(acc[t].y * inv);
        p1.x = __float2half_rn(acc[t].z * inv);
        p1.y = __float2half_rn(acc[t].w * inv);
        __half2 pk[2] = {p0, p1};
        *(uint2*)&dh[(lane + 32 * t) * 4] = *(uint2*)pk;   // one 8B store
    }
}

// ---------------------------------------------------------------------------
// Router: R11 warp microstructure (warp tile 32x64, double buffer, 2 syncs)
// scaled to CTA_M=128 x 512 threads, grid=128 -> one CTA per SM, balanced.
// + fused alpha / blend / head / l2 epilogue.
// ---------------------------------------------------------------------------
__device__ __forceinline__ void load_tiles(uint32_t st, int kk, int r0, int tid)
{
    const __half* ax = g_xh + (size_t)r0 * KX + kk;
    #pragma unroll
    for (int t = 0; t < 2; t++) {
        int idx = t * NT + tid;            // 1024 chunks: 128 rows x 8
        int r = idx >> 3, c = idx & 7;
        uint32_t sw = SWZ((uint32_t)(r * 128 + c * 16));
        cp16(st + OFF_A + sw, ax + (size_t)r * KX + c * 8);
    }
    const __half* bw = g_w1 + kk;
    #pragma unroll
    for (int t = 0; t < 4; t++) {
        int idx = t * NT + tid;            // 2048 chunks: 256 rows x 8
        int n = idx >> 3, c = idx & 7;
        uint32_t sw = SWZ((uint32_t)(n * 128 + c * 16));
        cp16(st + OFF_B + sw, bw + (size_t)n * KX + c * 8);
    }
}

__global__ __launch_bounds__(NT, 1) void router_kernel(
    const float* __restrict__ b1, const float* __restrict__ w2,
    const float* __restrict__ b2p,
    const float* __restrict__ headw, const float* __restrict__ headb,
    float* __restrict__ out)
{
    extern __shared__ char smem[];
    uint32_t sb = smem_u32(smem);
    int tid = threadIdx.x;
    int wid = tid >> 5, lane = tid & 31;
    int warp_m = wid >> 2;        // 0..3  (rows warp_m*32 .. +32)
    int warp_n = wid & 3;         // 0..3  (cols warp_n*64 .. +64)
    int r0 = blockIdx.x * CTA_M;

    float* s_b1    = (float*)(smem);           // 256 floats
    float* s_w2    = (float*)(smem + 1024);    // 256 floats
    float* s_part  = (float*)(smem + 2048);    // 128 floats
    float* s_alpha = (float*)(smem + 2560);    // 128 floats

    if (tid < H) { s_b1[tid] = b1[tid]; s_w2[tid] = w2[tid]; }
    if (tid >= NT - CTA_M) s_part[tid - (NT - CTA_M)] = 0.0f;
    float b2 = *b2p;

    // prologue: both stages
    load_tiles(sb + OFF_TILES, 0, r0, tid);
    CP_COMMIT();
    load_tiles(sb + OFF_TILES + STAGE_BYTES, KT2, r0, tid);
    CP_COMMIT();

    float acc[2][8][4];
    #pragma unroll
    for (int mi = 0; mi < 2; mi++)
        #pragma unroll
        for (int ni = 0; ni < 8; ni++)
            #pragma unroll
            for (int j = 0; j < 4; j++) acc[mi][ni][j] = 0.0f;

    // per-thread ldmatrix addressing (R11-validated formulas)
    int arow  = warp_m * 32 + (lane & 15);
    uint32_t acol = ((uint32_t)(lane >> 4)) * 16;
    int nrow  = warp_n * 64 + (((lane >> 4) & 1) << 3) + (lane & 7);
    uint32_t bcol = (((uint32_t)(lane >> 3)) & 1) << 4;

    for (int it = 0; it < NITER; it++) {
        if (it < NITER - 1)
            asm volatile("cp.async.wait_group 1;" ::: "memory");
        else
            asm volatile("cp.async.wait_group 0;" ::: "memory");
        __syncthreads();

        uint32_t st = sb + OFF_TILES + (uint32_t)(it & 1) * STAGE_BYTES;

        #pragma unroll
        for (int ks = 0; ks < 4; ks++) {
            uint32_t kb = (uint32_t)ks * 32;
            uint32_t aa[2][4];
            #pragma unroll
            for (int mi = 0; mi < 2; mi++) {
                uint32_t off = SWZ((uint32_t)((arow + mi * 16) * 128) + acol + kb);
                LDSM_X4(aa[mi], st + OFF_A + off);
            }
            uint32_t bb[8][2];
            #pragma unroll
            for (int g = 0; g < 4; g++) {
                uint32_t off = SWZ((uint32_t)((nrow + g * 16) * 128) + bcol + kb);
                uint32_t rb[4];
                LDSM_X4(rb, st + OFF_B + off);
                bb[2 * g][0] = rb[0]; bb[2 * g][1] = rb[1];
                bb[2 * g + 1][0] = rb[2]; bb[2 * g + 1][1] = rb[3];
            }
            #pragma unroll
            for (int mi = 0; mi < 2; mi++)
                #pragma unroll
                for (int ni = 0; ni < 8; ni++)
                    MMA_F16(acc[mi][ni], aa[mi], bb[ni]);
        }

        __syncthreads();
        if (it + 2 < NITER) {
            load_tiles(st, (it + 2) * KT2, r0, tid);
            CP_COMMIT();
        }
    }

    // alpha partials: relu(hdn + b1) . w2 over this warp's 64 columns
    #pragma unroll
    for (int mi = 0; mi < 2; mi++) {
        #pragma unroll
        for (int rh = 0; rh < 2; rh++) {
            float part = 0.0f;
            #pragma unroll
            for (int ni = 0; ni < 8; ni++) {
                int col0 = warp_n * 64 + ni * 8 + 2 * (lane & 3);
                float h0 = acc[mi][ni][rh * 2 + 0] + s_b1[col0];
                float h1 = acc[mi][ni][rh * 2 + 1] + s_b1[col0 + 1];
                h0 = h0 > 0.f ? h0 : 0.f;
                h1 = h1 > 0.f ? h1 : 0.f;
                part = fmaf(h0, s_w2[col0], part);
                part = fmaf(h1, s_w2[col0 + 1], part);
            }
            part += __shfl_xor_sync(0xffffffffu, part, 1);
            part += __shfl_xor_sync(0xffffffffu, part, 2);
            if ((lane & 3) == 0)
                atomicAdd(&s_part[warp_m * 32 + mi * 16 + rh * 8 + (lane >> 2)], part);
        }
    }
    __syncthreads();
    if (tid < CTA_M) {
        float z = s_part[tid] + b2;
        s_alpha[tid] = 1.0f / (1.0f + expf(-z));
    }
    __syncthreads();

    // blend/head/l2 epilogue: 16 warps x 8 words
    float* out_logits = out;
    float* out_alpha  = out + (size_t)ROWS * L;
    float* out_l2     = out_alpha + ROWS;

    #pragma unroll 1
    for (int wi = 0; wi < 8; wi++) {
        int li = wid * 8 + wi;
        size_t row = (size_t)(r0 + li);
        float al = s_alpha[li];
        float oma = 1.0f - al;
        const __half2* xh2 = (const __half2*)(g_xh + row * KX);

        float lg[L];
        #pragma unroll
        for (int l = 0; l < L; l++) lg[l] = 0.0f;
        float l2 = 0.0f;

        #pragma unroll 1
        for (int d2 = lane; d2 < D / 2; d2 += 32) {
            __half2 hh2 = xh2[d2];
            __half2 rr2 = xh2[D / 2 + d2];
            float hh[2], hr[2];
            hh[0] = __half2float(hh2.x); hh[1] = __half2float(hh2.y);
            hr[0] = __half2float(rr2.x); hr[1] = __half2float(rr2.y);
            #pragma unroll
            for (int u = 0; u < 2; u++) {
                int d = d2 * 2 + u;
                float bl = al * hh[u] + oma * hr[u];
                float df = hh[u] - hr[u];
                l2 = fmaf(df, df, l2);
                #pragma unroll
                for (int l = 0; l < L; l++)
                    lg[l] = fmaf(bl, headw[(size_t)d * L + l], lg[l]);
            }
        }
        #pragma unroll
        for (int o = 16; o > 0; o >>= 1) {
            #pragma unroll
            for (int l = 0; l < L; l++)
                lg[l] += __shfl_xor_sync(0xffffffffu, lg[l], o);
            l2 += __shfl_xor_sync(0xffffffffu, l2, o);
        }
        if (lane == 0) {
            #pragma unroll
            for (int l = 0; l < L; l++)
                out_logits[row * L + l] = lg[l] + headb[l];
            out_alpha[row] = al;
            out_l2[row] = sqrtf(l2);
        }
    }
}

extern "C" void kernel_launch(void* const* d_in, const int* in_sizes, int n_in,
                              void* d_out, int out_size)
{
    const float* hing = (const float*)d_in[0];
    const float* rob  = (const float*)d_in[1];
    const int*   hids = (const int*)d_in[2];
    const int*   rids = (const int*)d_in[3];
    // d_in[4] = num_words (unused by the reference outputs)
    const float* w1 = (const float*)d_in[5];
    const float* b1 = (const float*)d_in[6];
    const float* w2 = (const float*)d_in[7];
    const float* b2 = (const float*)d_in[8];
    const float* hw = (const float*)d_in[9];
    const float* hb = (const float*)d_in[10];
    float* out = (float*)d_out;

    cudaFuncSetAttribute(router_kernel,
                         cudaFuncAttributeMaxDynamicSharedMemorySize, SMEM_TOTAL);

    align_kernel<<<(ROWS * 2) / 8 + (KX * H) / 256, 256>>>(hing, rob, hids, rids, w1);
    router_kernel<<<ROWS / CTA_M, NT, SMEM_TOTAL>>>(b1, w2, b2, hw, hb, out);
}

// round 15
// speedup vs baseline: 1.4586x; 1.0856x over previous
#include <cuda_runtime.h>
#include <cuda_fp16.h>
#include <math.h>
#include <stdint.h>

#define BATCH 64
#define S 512
#define D 768
#define W 256
#define KX 1536     // 2*D router input
#define H 256       // router hidden (= GEMM N)
#define L 7
#define ROWS (BATCH * W)   // 16384
#define CTA_M 64
#define KT2 64             // K-tile (fp16 elems) = 128 bytes = one SW128 row
#define NITER (KX / KT2)   // 24

// stage layout (bytes): A 8K | B 32K
#define OFF_A 0u
#define OFF_B 8192u
#define STAGE_BYTES 40960u
#define OFF_TILES 4096u
#define SMEM_TOTAL (OFF_TILES + 2 * STAGE_BYTES)   // 86016 -> 2 CTAs/SM

// fp16 operands (single rounding)
__device__ __align__(16) __half g_xh[(size_t)ROWS * KX];
__device__ __align__(16) __half g_w1[(size_t)H * KX];   // [n][k]

__device__ __forceinline__ uint32_t smem_u32(const void* p) {
    uint32_t a;
    asm("{ .reg .u64 t; cvta.to.shared.u64 t, %1; cvt.u32.u64 %0, t; }"
        : "=r"(a) : "l"(p));
    return a;
}
#define SWZ(x) ((x) ^ (((x) >> 3) & 0x70))
__device__ __forceinline__ void cp16(uint32_t dst, const void* src) {
    asm volatile("cp.async.cg.shared.global [%0], [%1], 16;" :: "r"(dst), "l"(src));
}
#define CP_COMMIT() asm volatile("cp.async.commit_group;" ::: "memory")

#define LDSM_X4(R, A)                                                        \
    asm volatile("ldmatrix.sync.aligned.m8n8.x4.shared.b16 {%0,%1,%2,%3}, [%4];" \
        : "=r"((R)[0]), "=r"((R)[1]), "=r"((R)[2]), "=r"((R)[3]) : "r"(A))

#define MMA_F16(Dd, Aa, Bb)                                                  \
    asm volatile("mma.sync.aligned.m16n8k16.row.col.f32.f16.f16.f32 "        \
        "{%0,%1,%2,%3}, {%4,%5,%6,%7}, {%8,%9}, {%0,%1,%2,%3};"              \
        : "+f"((Dd)[0]), "+f"((Dd)[1]), "+f"((Dd)[2]), "+f"((Dd)[3])         \
        : "r"((Aa)[0]), "r"((Aa)[1]), "r"((Aa)[2]), "r"((Aa)[3]),            \
          "r"((Bb)[0]), "r"((Bb)[1]))

// ---------------------------------------------------------------------------
// Align + prep in ONE grid. One WARP per 8 consecutive words of one (b,src):
// single binary search + warp-uniform sequential sweep over the contiguous
// row range (~Poisson(16) rows), boundaries via ids[s]==w. 8x fewer searches,
// ~sqrt(8)x less per-warp imbalance, perfectly sequential streaming.
// Blocks >= 512 transpose/round their W1 chunk.
// ---------------------------------------------------------------------------
#define ALIGN_BLOCKS ((ROWS * 2) / 64)   // 512: 4096 warps, 8 words each
__global__ __launch_bounds__(256) void align_kernel(
    const float* __restrict__ hing, const float* __restrict__ rob,
    const int* __restrict__ hids, const int* __restrict__ rids,
    const float* __restrict__ w1)
{
    int tid = threadIdx.x;
    int bid = blockIdx.x;

    if (bid >= ALIGN_BLOCKS) {                      // prep_w1 blocks
        int idx = (bid - ALIGN_BLOCKS) * 256 + tid;     // n*KX + k
        int n = idx / KX;
        int k = idx - n * KX;
        g_w1[idx] = __float2half_rn(w1[(size_t)k * H + n]);
        return;
    }

    int unit = bid * 8 + (tid >> 5);   // 0 .. 4095
    int lane = tid & 31;
    int srci = unit & 1;
    int grp  = unit >> 1;              // 0 .. 2047
    int b  = grp >> 5;                 // batch row
    int w0 = (grp & 31) * 8;           // first word of this warp's group

    const int* ids = (srci ? rids : hids) + b * S;
    const float* src = srci ? rob : hing;
    const float4* base = (const float4*)(src + (size_t)b * S * D);

    // lower_bound(w0), 10 halving steps (range 512 -> 0)
    int lo = 0, h = S;
    #pragma unroll 1
    for (int i = 0; i < 10; i++) {
        int m = (lo + h) >> 1;
        int a = ids[m < S ? m : S - 1];
        if (lo < h) { if (a < w0) lo = m + 1; else h = m; }
    }

    int s = lo;
    #pragma unroll 1
    for (int wi = 0; wi < 8; wi++) {
        int w = w0 + wi;
        float4 acc[6];
        #pragma unroll
        for (int t = 0; t < 6; t++) acc[t] = make_float4(0.f, 0.f, 0.f, 0.f);
        int cnt = 0;
        #pragma unroll 1
        while (s < S && ids[s] == w) {       // warp-uniform
            const float4* rowp = base + (size_t)s * (D / 4) + lane;
            #pragma unroll
            for (int t = 0; t < 6; t++) {
                float4 v = rowp[32 * t];
                acc[t].x += v.x; acc[t].y += v.y;
                acc[t].z += v.z; acc[t].w += v.w;
            }
            s++; cnt++;
        }
        float inv = (cnt > 0) ? 1.0f / (float)cnt : 0.0f;
        __half* dh = g_xh + (size_t)(b * W + w) * KX + srci * D;
        #pragma unroll
        for (int t = 0; t < 6; t++) {
            __half2 p0, p1;
            p0.x = __float2half_rn(acc[t].x * inv);
            p0.y = __float2half_rn(acc[t].y * inv);
            p1.x = __float2half_rn(acc[t].z * inv);
            p1.y = __float2half_rn(acc[t].w * inv);
            __half2 pk[2] = {p0, p1};
            *(uint2*)&dh[(lane + 32 * t) * 4] = *(uint2*)pk;
        }
    }
}

// ---------------------------------------------------------------------------
// Router (R11 verbatim, measured 88.1us): mma.sync fp16 GEMM, CTA M=64 N=256
// K=1536, double-buffered cp.async, 2 CTAs/SM + fused epilogue.
// ---------------------------------------------------------------------------
__device__ __forceinline__ void load_tiles(uint32_t st, int kk, int r0, int tid)
{
    const __half* ax = g_xh + (size_t)r0 * KX + kk;
    #pragma unroll
    for (int t = 0; t < 2; t++) {
        int idx = t * 256 + tid;           // 512 chunks: 64 rows x 8
        int r = idx >> 3, c = idx & 7;
        uint32_t sw = SWZ((uint32_t)(r * 128 + c * 16));
        cp16(st + OFF_A + sw, ax + (size_t)r * KX + c * 8);
    }
    const __half* bw = g_w1 + kk;
    #pragma unroll
    for (int t = 0; t < 8; t++) {
        int idx = t * 256 + tid;           // 2048 chunks: 256 rows x 8
        int n = idx >> 3, c = idx & 7;
        uint32_t sw = SWZ((uint32_t)(n * 128 + c * 16));
        cp16(st + OFF_B + sw, bw + (size_t)n * KX + c * 8);
    }
}

__global__ __launch_bounds__(256, 2) void router_kernel(
    const float* __restrict__ b1, const float* __restrict__ w2,
    const float* __restrict__ b2p,
    const float* __restrict__ headw, const float* __restrict__ headb,
    float* __restrict__ out)
{
    extern __shared__ char smem[];
    uint32_t sb = smem_u32(smem);
    int tid = threadIdx.x;
    int wid = tid >> 5, lane = tid & 31;
    int warp_m = wid >> 2;        // 0..1  (rows warp_m*32 .. +32)
    int warp_n = wid & 3;         // 0..3  (cols warp_n*64 .. +64)
    int r0 = blockIdx.x * CTA_M;

    float* s_b1    = (float*)(smem);
    float* s_w2    = (float*)(smem + 1024);
    float* s_part  = (float*)(smem + 2048);   // 64 floats
    float* s_alpha = (float*)(smem + 2304);   // 64 floats

    s_b1[tid] = b1[tid];
    s_w2[tid] = w2[tid];
    if (tid < CTA_M) s_part[tid] = 0.0f;
    float b2 = *b2p;
    __syncthreads();

    // prologue: both stages
    load_tiles(sb + OFF_TILES, 0, r0, tid);
    CP_COMMIT();
    load_tiles(sb + OFF_TILES + STAGE_BYTES, KT2, r0, tid);
    CP_COMMIT();

    float acc[2][8][4];
    #pragma unroll
    for (int mi = 0; mi < 2; mi++)
        #pragma unroll
        for (int ni = 0; ni < 8; ni++)
            #pragma unroll
            for (int j = 0; j < 4; j++) acc[mi][ni][j] = 0.0f;

    // per-thread ldmatrix addressing (within tile, pre-swizzle parts)
    int arow  = warp_m * 32 + (lane & 15);
    uint32_t acol = ((uint32_t)(lane >> 4)) * 16;
    int nrow  = warp_n * 64 + (((lane >> 4) & 1) << 3) + (lane & 7);
    uint32_t bcol = (((uint32_t)(lane >> 3)) & 1) << 4;

    for (int it = 0; it < NITER; it++) {
        if (it < NITER - 1)
            asm volatile("cp.async.wait_group 1;" ::: "memory");
        else
            asm volatile("cp.async.wait_group 0;" ::: "memory");
        __syncthreads();

        uint32_t st = sb + OFF_TILES + (uint32_t)(it & 1) * STAGE_BYTES;

        #pragma unroll
        for (int ks = 0; ks < 4; ks++) {
            uint32_t kb = (uint32_t)ks * 32;
            uint32_t aa[2][4];
            #pragma unroll
            for (int mi = 0; mi < 2; mi++) {
                uint32_t off = SWZ((uint32_t)((arow + mi * 16) * 128) + acol + kb);
                LDSM_X4(aa[mi], st + OFF_A + off);
            }
            uint32_t bb[8][2];
            #pragma unroll
            for (int g = 0; g < 4; g++) {
                uint32_t off = SWZ((uint32_t)((nrow + g * 16) * 128) + bcol + kb);
                uint32_t rb[4];
                LDSM_X4(rb, st + OFF_B + off);
                bb[2 * g][0] = rb[0]; bb[2 * g][1] = rb[1];
                bb[2 * g + 1][0] = rb[2]; bb[2 * g + 1][1] = rb[3];
            }
            #pragma unroll
            for (int mi = 0; mi < 2; mi++)
                #pragma unroll
                for (int ni = 0; ni < 8; ni++)
                    MMA_F16(acc[mi][ni], aa[mi], bb[ni]);
        }

        __syncthreads();
        if (it + 2 < NITER) {
            load_tiles(st, (it + 2) * KT2, r0, tid);
            CP_COMMIT();
        }
    }

    // alpha partials: relu(hdn + b1) . w2 over this warp's 64 columns
    #pragma unroll
    for (int mi = 0; mi < 2; mi++) {
        #pragma unroll
        for (int rh = 0; rh < 2; rh++) {
            float part = 0.0f;
            #pragma unroll
            for (int ni = 0; ni < 8; ni++) {
                int col0 = warp_n * 64 + ni * 8 + 2 * (lane & 3);
                float h0 = acc[mi][ni][rh * 2 + 0] + s_b1[col0];
                float h1 = acc[mi][ni][rh * 2 + 1] + s_b1[col0 + 1];
                h0 = h0 > 0.f ? h0 : 0.f;
                h1 = h1 > 0.f ? h1 : 0.f;
                part = fmaf(h0, s_w2[col0], part);
                part = fmaf(h1, s_w2[col0 + 1], part);
            }
            part += __shfl_xor_sync(0xffffffffu, part, 1);
            part += __shfl_xor_sync(0xffffffffu, part, 2);
            if ((lane & 3) == 0)
                atomicAdd(&s_part[warp_m * 32 + mi * 16 + rh * 8 + (lane >> 2)], part);
        }
    }
    __syncthreads();
    if (tid < CTA_M) {
        float z = s_part[tid] + b2;
        s_alpha[tid] = 1.0f / (1.0f + expf(-z));
    }
    __syncthreads();

    // blend/head/l2 epilogue: 8 warps x 8 words
    float* out_logits = out;
    float* out_alpha  = out + (size_t)ROWS * L;
    float* out_l2     = out_alpha + ROWS;

    #pragma unroll 1
    for (int wi = 0; wi < 8; wi++) {
        int li = wid * 8 + wi;
        size_t row = (size_t)(r0 + li);
        float al = s_alpha[li];
        float oma = 1.0f - al;
        const __half2* xh2 = (const __half2*)(g_xh + row * KX);

        float lg[L];
        #pragma unroll
        for (int l = 0; l < L; l++) lg[l] = 0.0f;
        float l2 = 0.0f;

        #pragma unroll 1
        for (int d2 = lane; d2 < D / 2; d2 += 32) {
            __half2 hh2 = xh2[d2];
            __half2 rr2 = xh2[D / 2 + d2];
            float hh[2], hr[2];
            hh[0] = __half2float(hh2.x); hh[1] = __half2float(hh2.y);
            hr[0] = __half2float(rr2.x); hr[1] = __half2float(rr2.y);
            #pragma unroll
            for (int u = 0; u < 2; u++) {
                int d = d2 * 2 + u;
                float bl = al * hh[u] + oma * hr[u];
                float df = hh[u] - hr[u];
                l2 = fmaf(df, df, l2);
                #pragma unroll
                for (int l = 0; l < L; l++)
                    lg[l] = fmaf(bl, headw[(size_t)d * L + l], lg[l]);
            }
        }
        #pragma unroll
        for (int o = 16; o > 0; o >>= 1) {
            #pragma unroll
            for (int l = 0; l < L; l++)
                lg[l] += __shfl_xor_sync(0xffffffffu, lg[l], o);
            l2 += __shfl_xor_sync(0xffffffffu, l2, o);
        }
        if (lane == 0) {
            #pragma unroll
            for (int l = 0; l < L; l++)
                out_logits[row * L + l] = lg[l] + headb[l];
            out_alpha[row] = al;
            out_l2[row] = sqrtf(l2);
        }
    }
}

extern "C" void kernel_launch(void* const* d_in, const int* in_sizes, int n_in,
                              void* d_out, int out_size)
{
    const float* hing = (const float*)d_in[0];
    const float* rob  = (const float*)d_in[1];
    const int*   hids = (const int*)d_in[2];
    const int*   rids = (const int*)d_in[3];
    // d_in[4] = num_words (unused by the reference outputs)
    const float* w1 = (const float*)d_in[5];
    const float* b1 = (const float*)d_in[6];
    const float* w2 = (const float*)d_in[7];
    const float* b2 = (const float*)d_in[8];
    const float* hw = (const float*)d_in[9];
    const float* hb = (const float*)d_in[10];
    float* out = (float*)d_out;

    cudaFuncSetAttribute(router_kernel,
                         cudaFuncAttributeMaxDynamicSharedMemorySize, SMEM_TOTAL);

    align_kernel<<<ALIGN_BLOCKS + (KX * H) / 256, 256>>>(hing, rob, hids, rids, w1);
    router_kernel<<<ROWS / CTA_M, 256, SMEM_TOTAL>>>(b1, w2, b2, hw, hb, out);
}

// round 16
// speedup vs baseline: 1.6263x; 1.1150x over previous
#include <cuda_runtime.h>
#include <cuda_fp16.h>
#include <math.h>
#include <stdint.h>

#define BATCH 64
#define S 512
#define D 768
#define W 256
#define KX 1536     // 2*D router input
#define H 256       // router hidden (= GEMM N)
#define L 7
#define ROWS (BATCH * W)   // 16384
#define CTA_M 64
#define KT2 64             // K-tile (fp16 elems) = 128 bytes = one SW128 row
#define NITER (KX / KT2)   // 24

// stage layout (bytes): A 8K | B 32K
#define OFF_A 0u
#define OFF_B 8192u
#define STAGE_BYTES 40960u
#define OFF_TILES 4096u
#define SMEM_TOTAL (OFF_TILES + 2 * STAGE_BYTES)   // 86016 -> 2 CTAs/SM

// fp16 operands (single rounding)
__device__ __align__(16) __half g_xh[(size_t)ROWS * KX];
__device__ __align__(16) __half g_w1[(size_t)H * KX];   // [n][k]
// per-(row, source) head projections from fp32 means: [row][src*8 + l]
__device__ float g_hw[(size_t)ROWS * 16];

__device__ __forceinline__ uint32_t smem_u32(const void* p) {
    uint32_t a;
    asm("{ .reg .u64 t; cvta.to.shared.u64 t, %1; cvt.u32.u64 %0, t; }"
        : "=r"(a) : "l"(p));
    return a;
}
#define SWZ(x) ((x) ^ (((x) >> 3) & 0x70))
__device__ __forceinline__ void cp16(uint32_t dst, const void* src) {
    asm volatile("cp.async.cg.shared.global [%0], [%1], 16;" :: "r"(dst), "l"(src));
}
#define CP_COMMIT() asm volatile("cp.async.commit_group;" ::: "memory")

#define LDSM_X4(R, A)                                                        \
    asm volatile("ldmatrix.sync.aligned.m8n8.x4.shared.b16 {%0,%1,%2,%3}, [%4];" \
        : "=r"((R)[0]), "=r"((R)[1]), "=r"((R)[2]), "=r"((R)[3]) : "r"(A))

#define MMA_F16(Dd, Aa, Bb)                                                  \
    asm volatile("mma.sync.aligned.m16n8k16.row.col.f32.f16.f16.f32 "        \
        "{%0,%1,%2,%3}, {%4,%5,%6,%7}, {%8,%9}, {%0,%1,%2,%3};"              \
        : "+f"((Dd)[0]), "+f"((Dd)[1]), "+f"((Dd)[2]), "+f"((Dd)[3])         \
        : "r"((Aa)[0]), "r"((Aa)[1]), "r"((Aa)[2]), "r"((Aa)[3]),            \
          "r"((Bb)[0]), "r"((Bb)[1]))

// ---------------------------------------------------------------------------
// Align + prep in ONE grid. One WARP per 8 consecutive words of one (b,src):
// single binary search + warp-uniform sequential sweep (R15, proven).
// NEW: per word, also compute the 7 head projections h.headw from the fp32
// means (transposed headw in smem, conflict-free float4 LDS) -> g_hw.
// Blocks >= ALIGN_BLOCKS transpose/round their W1 chunk.
// ---------------------------------------------------------------------------
#define ALIGN_BLOCKS ((ROWS * 2) / 64)   // 512: 4096 warps, 8 words each
__global__ __launch_bounds__(256) void align_kernel(
    const float* __restrict__ hing, const float* __restrict__ rob,
    const int* __restrict__ hids, const int* __restrict__ rids,
    const float* __restrict__ w1, const float* __restrict__ headw)
{
    __shared__ float s_hwT[L * D];   // transposed headw: [l][d], 21504 B

    int tid = threadIdx.x;
    int bid = blockIdx.x;

    if (bid >= ALIGN_BLOCKS) {                      // prep_w1 blocks
        int idx = (bid - ALIGN_BLOCKS) * 256 + tid;     // n*KX + k
        int n = idx / KX;
        int k = idx - n * KX;
        g_w1[idx] = __float2half_rn(w1[(size_t)k * H + n]);
        return;
    }

    // load transposed headw into smem
    for (int i = tid; i < L * D; i += 256) {
        int l = i / D;
        int d = i - l * D;
        s_hwT[i] = headw[(size_t)d * L + l];
    }
    __syncthreads();

    int unit = bid * 8 + (tid >> 5);   // 0 .. 4095
    int lane = tid & 31;
    int srci = unit & 1;
    int grp  = unit >> 1;              // 0 .. 2047
    int b  = grp >> 5;                 // batch row
    int w0 = (grp & 31) * 8;           // first word of this warp's group

    const int* ids = (srci ? rids : hids) + b * S;
    const float* src = srci ? rob : hing;
    const float4* base = (const float4*)(src + (size_t)b * S * D);

    // lower_bound(w0), 10 halving steps (range 512 -> 0)
    int lo = 0, h = S;
    #pragma unroll 1
    for (int i = 0; i < 10; i++) {
        int m = (lo + h) >> 1;
        int a = ids[m < S ? m : S - 1];
        if (lo < h) { if (a < w0) lo = m + 1; else h = m; }
    }

    int s = lo;
    #pragma unroll 1
    for (int wi = 0; wi < 8; wi++) {
        int w = w0 + wi;
        float4 acc[6];
        #pragma unroll
        for (int t = 0; t < 6; t++) acc[t] = make_float4(0.f, 0.f, 0.f, 0.f);
        int cnt = 0;
        #pragma unroll 1
        while (s < S && ids[s] == w) {       // warp-uniform
            const float4* rowp = base + (size_t)s * (D / 4) + lane;
            #pragma unroll
            for (int t = 0; t < 6; t++) {
                float4 v = rowp[32 * t];
                acc[t].x += v.x; acc[t].y += v.y;
                acc[t].z += v.z; acc[t].w += v.w;
            }
            s++; cnt++;
        }
        float inv = (cnt > 0) ? 1.0f / (float)cnt : 0.0f;
        __half* dh = g_xh + (size_t)(b * W + w) * KX + srci * D;

        float p[L];
        #pragma unroll
        for (int l = 0; l < L; l++) p[l] = 0.0f;

        #pragma unroll
        for (int t = 0; t < 6; t++) {
            float mx = acc[t].x * inv, my = acc[t].y * inv;
            float mz = acc[t].z * inv, mw = acc[t].w * inv;
            // fp16 mean for GEMM A / l2
            __half2 p0, p1;
            p0.x = __float2half_rn(mx); p0.y = __float2half_rn(my);
            p1.x = __float2half_rn(mz); p1.y = __float2half_rn(mw);
            __half2 pk[2] = {p0, p1};
            *(uint2*)&dh[(lane + 32 * t) * 4] = *(uint2*)pk;
            // head projections from fp32 mean
            int dbase = (lane + 32 * t) * 4;
            #pragma unroll
            for (int l = 0; l < L; l++) {
                float4 hv = *(const float4*)&s_hwT[l * D + dbase];
                p[l] = fmaf(mx, hv.x, p[l]);
                p[l] = fmaf(my, hv.y, p[l]);
                p[l] = fmaf(mz, hv.z, p[l]);
                p[l] = fmaf(mw, hv.w, p[l]);
            }
        }
        #pragma unroll
        for (int l = 0; l < L; l++)
            #pragma unroll
            for (int o = 16; o > 0; o >>= 1)
                p[l] += __shfl_xor_sync(0xffffffffu, p[l], o);
        if (lane == 0) {
            float* outp = g_hw + (size_t)(b * W + w) * 16 + srci * 8;
            #pragma unroll
            for (int l = 0; l < L; l++) outp[l] = p[l];
        }
    }
}

// ---------------------------------------------------------------------------
// Router (R11 mainloop verbatim, 88.1us measured): mma.sync fp16 GEMM,
// CTA M=64 N=256 K=1536, double-buffered cp.async, 2 CTAs/SM.
// Epilogue now: alpha + l2 elementwise + logits from g_hw (head FMAs gone).
// ---------------------------------------------------------------------------
__device__ __forceinline__ void load_tiles(uint32_t st, int kk, int r0, int tid)
{
    const __half* ax = g_xh + (size_t)r0 * KX + kk;
    #pragma unroll
    for (int t = 0; t < 2; t++) {
        int idx = t * 256 + tid;           // 512 chunks: 64 rows x 8
        int r = idx >> 3, c = idx & 7;
        uint32_t sw = SWZ((uint32_t)(r * 128 + c * 16));
        cp16(st + OFF_A + sw, ax + (size_t)r * KX + c * 8);
    }
    const __half* bw = g_w1 + kk;
    #pragma unroll
    for (int t = 0; t < 8; t++) {
        int idx = t * 256 + tid;           // 2048 chunks: 256 rows x 8
        int n = idx >> 3, c = idx & 7;
        uint32_t sw = SWZ((uint32_t)(n * 128 + c * 16));
        cp16(st + OFF_B + sw, bw + (size_t)n * KX + c * 8);
    }
}

__global__ __launch_bounds__(256, 2) void router_kernel(
    const float* __restrict__ b1, const float* __restrict__ w2,
    const float* __restrict__ b2p,
    const float* __restrict__ headb,
    float* __restrict__ out)
{
    extern __shared__ char smem[];
    uint32_t sb = smem_u32(smem);
    int tid = threadIdx.x;
    int wid = tid >> 5, lane = tid & 31;
    int warp_m = wid >> 2;        // 0..1  (rows warp_m*32 .. +32)
    int warp_n = wid & 3;         // 0..3  (cols warp_n*64 .. +64)
    int r0 = blockIdx.x * CTA_M;

    float* s_b1    = (float*)(smem);
    float* s_w2    = (float*)(smem + 1024);
    float* s_part  = (float*)(smem + 2048);   // 64 floats
    float* s_alpha = (float*)(smem + 2304);   // 64 floats

    s_b1[tid] = b1[tid];
    s_w2[tid] = w2[tid];
    if (tid < CTA_M) s_part[tid] = 0.0f;
    float b2 = *b2p;
    __syncthreads();

    // prologue: both stages
    load_tiles(sb + OFF_TILES, 0, r0, tid);
    CP_COMMIT();
    load_tiles(sb + OFF_TILES + STAGE_BYTES, KT2, r0, tid);
    CP_COMMIT();

    float acc[2][8][4];
    #pragma unroll
    for (int mi = 0; mi < 2; mi++)
        #pragma unroll
        for (int ni = 0; ni < 8; ni++)
            #pragma unroll
            for (int j = 0; j < 4; j++) acc[mi][ni][j] = 0.0f;

    // per-thread ldmatrix addressing (within tile, pre-swizzle parts)
    int arow  = warp_m * 32 + (lane & 15);
    uint32_t acol = ((uint32_t)(lane >> 4)) * 16;
    int nrow  = warp_n * 64 + (((lane >> 4) & 1) << 3) + (lane & 7);
    uint32_t bcol = (((uint32_t)(lane >> 3)) & 1) << 4;

    for (int it = 0; it < NITER; it++) {
        if (it < NITER - 1)
            asm volatile("cp.async.wait_group 1;" ::: "memory");
        else
            asm volatile("cp.async.wait_group 0;" ::: "memory");
        __syncthreads();

        uint32_t st = sb + OFF_TILES + (uint32_t)(it & 1) * STAGE_BYTES;

        #pragma unroll
        for (int ks = 0; ks < 4; ks++) {
            uint32_t kb = (uint32_t)ks * 32;
            uint32_t aa[2][4];
            #pragma unroll
            for (int mi = 0; mi < 2; mi++) {
                uint32_t off = SWZ((uint32_t)((arow + mi * 16) * 128) + acol + kb);
                LDSM_X4(aa[mi], st + OFF_A + off);
            }
            uint32_t bb[8][2];
            #pragma unroll
            for (int g = 0; g < 4; g++) {
                uint32_t off = SWZ((uint32_t)((nrow + g * 16) * 128) + bcol + kb);
                uint32_t rb[4];
                LDSM_X4(rb, st + OFF_B + off);
                bb[2 * g][0] = rb[0]; bb[2 * g][1] = rb[1];
                bb[2 * g + 1][0] = rb[2]; bb[2 * g + 1][1] = rb[3];
            }
            #pragma unroll
            for (int mi = 0; mi < 2; mi++)
                #pragma unroll
                for (int ni = 0; ni < 8; ni++)
                    MMA_F16(acc[mi][ni], aa[mi], bb[ni]);
        }

        __syncthreads();
        if (it + 2 < NITER) {
            load_tiles(st, (it + 2) * KT2, r0, tid);
            CP_COMMIT();
        }
    }

    // alpha partials: relu(hdn + b1) . w2 over this warp's 64 columns
    #pragma unroll
    for (int mi = 0; mi < 2; mi++) {
        #pragma unroll
        for (int rh = 0; rh < 2; rh++) {
            float part = 0.0f;
            #pragma unroll
            for (int ni = 0; ni < 8; ni++) {
                int col0 = warp_n * 64 + ni * 8 + 2 * (lane & 3);
                float h0 = acc[mi][ni][rh * 2 + 0] + s_b1[col0];
                float h1 = acc[mi][ni][rh * 2 + 1] + s_b1[col0 + 1];
                h0 = h0 > 0.f ? h0 : 0.f;
                h1 = h1 > 0.f ? h1 : 0.f;
                part = fmaf(h0, s_w2[col0], part);
                part = fmaf(h1, s_w2[col0 + 1], part);
            }
            part += __shfl_xor_sync(0xffffffffu, part, 1);
            part += __shfl_xor_sync(0xffffffffu, part, 2);
            if ((lane & 3) == 0)
                atomicAdd(&s_part[warp_m * 32 + mi * 16 + rh * 8 + (lane >> 2)], part);
        }
    }
    __syncthreads();
    if (tid < CTA_M) {
        float z = s_part[tid] + b2;
        s_alpha[tid] = 1.0f / (1.0f + expf(-z));
    }
    __syncthreads();

    // epilogue: alpha + l2 (elementwise) + logits from g_hw
    float* out_logits = out;
    float* out_alpha  = out + (size_t)ROWS * L;
    float* out_l2     = out_alpha + ROWS;

    #pragma unroll 1
    for (int wi = 0; wi < 8; wi++) {
        int li = wid * 8 + wi;
        size_t row = (size_t)(r0 + li);
        float al = s_alpha[li];
        const __half2* xh2 = (const __half2*)(g_xh + row * KX);

        float l2 = 0.0f;
        #pragma unroll 1
        for (int d2 = lane; d2 < D / 2; d2 += 32) {
            __half2 hh2 = xh2[d2];
            __half2 rr2 = xh2[D / 2 + d2];
            float d0 = __half2float(hh2.x) - __half2float(rr2.x);
            float d1 = __half2float(hh2.y) - __half2float(rr2.y);
            l2 = fmaf(d0, d0, l2);
            l2 = fmaf(d1, d1, l2);
        }
        #pragma unroll
        for (int o = 16; o > 0; o >>= 1)
            l2 += __shfl_xor_sync(0xffffffffu, l2, o);

        if (lane < L) {
            float hwh = g_hw[row * 16 + lane];
            float hwr = g_hw[row * 16 + 8 + lane];
            out_logits[row * L + lane] =
                fmaf(al, hwh, fmaf(1.0f - al, hwr, headb[lane]));
        }
        if (lane == 0) {
            out_alpha[row] = al;
            out_l2[row] = sqrtf(l2);
        }
    }
}

extern "C" void kernel_launch(void* const* d_in, const int* in_sizes, int n_in,
                              void* d_out, int out_size)
{
    const float* hing = (const float*)d_in[0];
    const float* rob  = (const float*)d_in[1];
    const int*   hids = (const int*)d_in[2];
    const int*   rids = (const int*)d_in[3];
    // d_in[4] = num_words (unused by the reference outputs)
    const float* w1 = (const float*)d_in[5];
    const float* b1 = (const float*)d_in[6];
    const float* w2 = (const float*)d_in[7];
    const float* b2 = (const float*)d_in[8];
    const float* hw = (const float*)d_in[9];
    const float* hb = (const float*)d_in[10];
    float* out = (float*)d_out;

    cudaFuncSetAttribute(router_kernel,
                         cudaFuncAttributeMaxDynamicSharedMemorySize, SMEM_TOTAL);

    align_kernel<<<ALIGN_BLOCKS + (KX * H) / 256, 256>>>(hing, rob, hids, rids, w1, hw);
    router_kernel<<<ROWS / CTA_M, 256, SMEM_TOTAL>>>(b1, w2, b2, hb, out);
}

// round 17
// speedup vs baseline: 1.6740x; 1.0293x over previous
#include <cuda_runtime.h>
#include <cuda_fp16.h>
#include <math.h>
#include <stdint.h>

#define BATCH 64
#define S 512
#define D 768
#define W 256
#define KX 1536     // 2*D router input
#define H 256       // router hidden (= GEMM N)
#define L 7
#define ROWS (BATCH * W)   // 16384
#define CTA_M 64
#define KT2 64             // K-tile (fp16 elems) = 128 bytes = one SW128 row
#define NITER (KX / KT2)   // 24

// stage layout (bytes): A 8K | B 32K
#define OFF_A 0u
#define OFF_B 8192u
#define STAGE_BYTES 40960u
#define OFF_TILES 4096u
#define SMEM_TOTAL (OFF_TILES + 2 * STAGE_BYTES)   // 86016 -> 2 CTAs/SM

// fp16 operands (single rounding)
__device__ __align__(16) __half g_xh[(size_t)ROWS * KX];
__device__ __align__(16) __half g_w1[(size_t)H * KX];   // [n][k]
// per-(row, source) head projections from fp32 means: [row][src*8 + l]
__device__ float g_hw[(size_t)ROWS * 16];

__device__ __forceinline__ uint32_t smem_u32(const void* p) {
    uint32_t a;
    asm("{ .reg .u64 t; cvta.to.shared.u64 t, %1; cvt.u32.u64 %0, t; }"
        : "=r"(a) : "l"(p));
    return a;
}
#define SWZ(x) ((x) ^ (((x) >> 3) & 0x70))
__device__ __forceinline__ void cp16(uint32_t dst, const void* src) {
    asm volatile("cp.async.cg.shared.global [%0], [%1], 16;" :: "r"(dst), "l"(src));
}
#define CP_COMMIT() asm volatile("cp.async.commit_group;" ::: "memory")

#define LDSM_X4(R, A)                                                        \
    asm volatile("ldmatrix.sync.aligned.m8n8.x4.shared.b16 {%0,%1,%2,%3}, [%4];" \
        : "=r"((R)[0]), "=r"((R)[1]), "=r"((R)[2]), "=r"((R)[3]) : "r"(A))

#define MMA_F16(Dd, Aa, Bb)                                                  \
    asm volatile("mma.sync.aligned.m16n8k16.row.col.f32.f16.f16.f32 "        \
        "{%0,%1,%2,%3}, {%4,%5,%6,%7}, {%8,%9}, {%0,%1,%2,%3};"              \
        : "+f"((Dd)[0]), "+f"((Dd)[1]), "+f"((Dd)[2]), "+f"((Dd)[3])         \
        : "r"((Aa)[0]), "r"((Aa)[1]), "r"((Aa)[2]), "r"((Aa)[3]),            \
          "r"((Bb)[0]), "r"((Bb)[1]))

// ---------------------------------------------------------------------------
// Align + prep in ONE grid. One WARP per 8 consecutive words, BOTH sources
// (sequential sweeps with independent cursors): fp16 means -> g_xh, head
// projections from fp32 means -> g_hw, and l2 disagreement from fp32 means
// written DIRECTLY to out_l2. Blocks >= ALIGN_BLOCKS transpose/round W1.
// ---------------------------------------------------------------------------
#define ALIGN_BLOCKS (ROWS / 64)   // 256 blocks: 2048 warps x 8 words x 2 srcs
__global__ __launch_bounds__(256) void align_kernel(
    const float* __restrict__ hing, const float* __restrict__ rob,
    const int* __restrict__ hids, const int* __restrict__ rids,
    const float* __restrict__ w1, const float* __restrict__ headw,
    float* __restrict__ out)
{
    __shared__ float s_hwT[L * D];   // transposed headw: [l][d], 21504 B

    int tid = threadIdx.x;
    int bid = blockIdx.x;

    if (bid >= ALIGN_BLOCKS) {                      // prep_w1 blocks
        int idx = (bid - ALIGN_BLOCKS) * 256 + tid;     // n*KX + k
        int n = idx / KX;
        int k = idx - n * KX;
        g_w1[idx] = __float2half_rn(w1[(size_t)k * H + n]);
        return;
    }

    // load transposed headw into smem
    for (int i = tid; i < L * D; i += 256) {
        int l = i / D;
        int d = i - l * D;
        s_hwT[i] = headw[(size_t)d * L + l];
    }
    __syncthreads();

    int grp  = bid * 8 + (tid >> 5);   // 0 .. 2047
    int lane = tid & 31;
    int b  = grp >> 5;                 // batch row
    int w0 = (grp & 31) * 8;           // first word of this warp's group

    const int* ids0 = hids + b * S;
    const int* ids1 = rids + b * S;
    const float4* base0 = (const float4*)(hing + (size_t)b * S * D);
    const float4* base1 = (const float4*)(rob  + (size_t)b * S * D);

    // interleaved lower_bound(w0) in both id arrays, 10 halving steps
    int lo0 = 0, h0 = S, lo1 = 0, h1 = S;
    #pragma unroll 1
    for (int i = 0; i < 10; i++) {
        int m0 = (lo0 + h0) >> 1, m1 = (lo1 + h1) >> 1;
        int a0 = ids0[m0 < S ? m0 : S - 1];
        int a1 = ids1[m1 < S ? m1 : S - 1];
        if (lo0 < h0) { if (a0 < w0) lo0 = m0 + 1; else h0 = m0; }
        if (lo1 < h1) { if (a1 < w0) lo1 = m1 + 1; else h1 = m1; }
    }

    float* out_l2 = out + (size_t)ROWS * L + ROWS;

    int s0 = lo0, s1 = lo1;
    #pragma unroll 1
    for (int wi = 0; wi < 8; wi++) {
        int w = w0 + wi;
        float4 a0c[6], a1c[6];
        #pragma unroll
        for (int t = 0; t < 6; t++) {
            a0c[t] = make_float4(0.f, 0.f, 0.f, 0.f);
            a1c[t] = make_float4(0.f, 0.f, 0.f, 0.f);
        }
        int c0 = 0, c1 = 0;
        #pragma unroll 1
        while (s0 < S && ids0[s0] == w) {      // warp-uniform
            const float4* rowp = base0 + (size_t)s0 * (D / 4) + lane;
            #pragma unroll
            for (int t = 0; t < 6; t++) {
                float4 v = rowp[32 * t];
                a0c[t].x += v.x; a0c[t].y += v.y;
                a0c[t].z += v.z; a0c[t].w += v.w;
            }
            s0++; c0++;
        }
        #pragma unroll 1
        while (s1 < S && ids1[s1] == w) {      // warp-uniform
            const float4* rowp = base1 + (size_t)s1 * (D / 4) + lane;
            #pragma unroll
            for (int t = 0; t < 6; t++) {
                float4 v = rowp[32 * t];
                a1c[t].x += v.x; a1c[t].y += v.y;
                a1c[t].z += v.z; a1c[t].w += v.w;
            }
            s1++; c1++;
        }
        float inv0 = (c0 > 0) ? 1.0f / (float)c0 : 0.0f;
        float inv1 = (c1 > 0) ? 1.0f / (float)c1 : 0.0f;

        size_t row = (size_t)(b * W + w);
        __half* dh = g_xh + row * KX;

        float p0[L], p1[L];
        #pragma unroll
        for (int l = 0; l < L; l++) { p0[l] = 0.0f; p1[l] = 0.0f; }
        float l2p = 0.0f;

        #pragma unroll
        for (int t = 0; t < 6; t++) {
            float m0x = a0c[t].x * inv0, m0y = a0c[t].y * inv0;
            float m0z = a0c[t].z * inv0, m0w = a0c[t].w * inv0;
            float m1x = a1c[t].x * inv1, m1y = a1c[t].y * inv1;
            float m1z = a1c[t].z * inv1, m1w = a1c[t].w * inv1;

            int dbase = (lane + 32 * t) * 4;
            // fp16 means for the GEMM A operand
            __half2 q0, q1;
            q0.x = __float2half_rn(m0x); q0.y = __float2half_rn(m0y);
            q1.x = __float2half_rn(m0z); q1.y = __float2half_rn(m0w);
            __half2 pk0[2] = {q0, q1};
            *(uint2*)&dh[dbase] = *(uint2*)pk0;
            q0.x = __float2half_rn(m1x); q0.y = __float2half_rn(m1y);
            q1.x = __float2half_rn(m1z); q1.y = __float2half_rn(m1w);
            __half2 pk1[2] = {q0, q1};
            *(uint2*)&dh[D + dbase] = *(uint2*)pk1;

            // head projections (fp32 means)
            #pragma unroll
            for (int l = 0; l < L; l++) {
                float4 hv = *(const float4*)&s_hwT[l * D + dbase];
                p0[l] = fmaf(m0x, hv.x, p0[l]);
                p0[l] = fmaf(m0y, hv.y, p0[l]);
                p0[l] = fmaf(m0z, hv.z, p0[l]);
                p0[l] = fmaf(m0w, hv.w, p0[l]);
                p1[l] = fmaf(m1x, hv.x, p1[l]);
                p1[l] = fmaf(m1y, hv.y, p1[l]);
                p1[l] = fmaf(m1z, hv.z, p1[l]);
                p1[l] = fmaf(m1w, hv.w, p1[l]);
            }
            // l2 disagreement (fp32 means)
            float d0 = m0x - m1x, d1 = m0y - m1y;
            float d2 = m0z - m1z, d3 = m0w - m1w;
            l2p = fmaf(d0, d0, l2p);
            l2p = fmaf(d1, d1, l2p);
            l2p = fmaf(d2, d2, l2p);
            l2p = fmaf(d3, d3, l2p);
        }
        #pragma unroll
        for (int o = 16; o > 0; o >>= 1) {
            #pragma unroll
            for (int l = 0; l < L; l++) {
                p0[l] += __shfl_xor_sync(0xffffffffu, p0[l], o);
                p1[l] += __shfl_xor_sync(0xffffffffu, p1[l], o);
            }
            l2p += __shfl_xor_sync(0xffffffffu, l2p, o);
        }
        if (lane == 0) {
            float* outp = g_hw + row * 16;
            #pragma unroll
            for (int l = 0; l < L; l++) { outp[l] = p0[l]; outp[8 + l] = p1[l]; }
            out_l2[row] = sqrtf(l2p);
        }
    }
}

// ---------------------------------------------------------------------------
// Router (R11 mainloop verbatim): mma.sync fp16 GEMM, CTA M=64 N=256 K=1536,
// double-buffered cp.async, 2 CTAs/SM. Epilogue now TRIVIAL: alpha + logits
// from g_hw + alpha store. (l2 handled entirely by align.)
// ---------------------------------------------------------------------------
__device__ __forceinline__ void load_tiles(uint32_t st, int kk, int r0, int tid)
{
    const __half* ax = g_xh + (size_t)r0 * KX + kk;
    #pragma unroll
    for (int t = 0; t < 2; t++) {
        int idx = t * 256 + tid;           // 512 chunks: 64 rows x 8
        int r = idx >> 3, c = idx & 7;
        uint32_t sw = SWZ((uint32_t)(r * 128 + c * 16));
        cp16(st + OFF_A + sw, ax + (size_t)r * KX + c * 8);
    }
    const __half* bw = g_w1 + kk;
    #pragma unroll
    for (int t = 0; t < 8; t++) {
        int idx = t * 256 + tid;           // 2048 chunks: 256 rows x 8
        int n = idx >> 3, c = idx & 7;
        uint32_t sw = SWZ((uint32_t)(n * 128 + c * 16));
        cp16(st + OFF_B + sw, bw + (size_t)n * KX + c * 8);
    }
}

__global__ __launch_bounds__(256, 2) void router_kernel(
    const float* __restrict__ b1, const float* __restrict__ w2,
    const float* __restrict__ b2p,
    const float* __restrict__ headb,
    float* __restrict__ out)
{
    extern __shared__ char smem[];
    uint32_t sb = smem_u32(smem);
    int tid = threadIdx.x;
    int wid = tid >> 5, lane = tid & 31;
    int warp_m = wid >> 2;        // 0..1  (rows warp_m*32 .. +32)
    int warp_n = wid & 3;         // 0..3  (cols warp_n*64 .. +64)
    int r0 = blockIdx.x * CTA_M;

    float* s_b1    = (float*)(smem);
    float* s_w2    = (float*)(smem + 1024);
    float* s_part  = (float*)(smem + 2048);   // 64 floats
    float* s_alpha = (float*)(smem + 2304);   // 64 floats

    s_b1[tid] = b1[tid];
    s_w2[tid] = w2[tid];
    if (tid < CTA_M) s_part[tid] = 0.0f;
    float b2 = *b2p;
    __syncthreads();

    // prologue: both stages
    load_tiles(sb + OFF_TILES, 0, r0, tid);
    CP_COMMIT();
    load_tiles(sb + OFF_TILES + STAGE_BYTES, KT2, r0, tid);
    CP_COMMIT();

    float acc[2][8][4];
    #pragma unroll
    for (int mi = 0; mi < 2; mi++)
        #pragma unroll
        for (int ni = 0; ni < 8; ni++)
            #pragma unroll
            for (int j = 0; j < 4; j++) acc[mi][ni][j] = 0.0f;

    // per-thread ldmatrix addressing (within tile, pre-swizzle parts)
    int arow  = warp_m * 32 + (lane & 15);
    uint32_t acol = ((uint32_t)(lane >> 4)) * 16;
    int nrow  = warp_n * 64 + (((lane >> 4) & 1) << 3) + (lane & 7);
    uint32_t bcol = (((uint32_t)(lane >> 3)) & 1) << 4;

    for (int it = 0; it < NITER; it++) {
        if (it < NITER - 1)
            asm volatile("cp.async.wait_group 1;" ::: "memory");
        else
            asm volatile("cp.async.wait_group 0;" ::: "memory");
        __syncthreads();

        uint32_t st = sb + OFF_TILES + (uint32_t)(it & 1) * STAGE_BYTES;

        #pragma unroll
        for (int ks = 0; ks < 4; ks++) {
            uint32_t kb = (uint32_t)ks * 32;
            uint32_t aa[2][4];
            #pragma unroll
            for (int mi = 0; mi < 2; mi++) {
                uint32_t off = SWZ((uint32_t)((arow + mi * 16) * 128) + acol + kb);
                LDSM_X4(aa[mi], st + OFF_A + off);
            }
            uint32_t bb[8][2];
            #pragma unroll
            for (int g = 0; g < 4; g++) {
                uint32_t off = SWZ((uint32_t)((nrow + g * 16) * 128) + bcol + kb);
                uint32_t rb[4];
                LDSM_X4(rb, st + OFF_B + off);
                bb[2 * g][0] = rb[0]; bb[2 * g][1] = rb[1];
                bb[2 * g + 1][0] = rb[2]; bb[2 * g + 1][1] = rb[3];
            }
            #pragma unroll
            for (int mi = 0; mi < 2; mi++)
                #pragma unroll
                for (int ni = 0; ni < 8; ni++)
                    MMA_F16(acc[mi][ni], aa[mi], bb[ni]);
        }

        __syncthreads();
        if (it + 2 < NITER) {
            load_tiles(st, (it + 2) * KT2, r0, tid);
            CP_COMMIT();
        }
    }

    // alpha partials: relu(hdn + b1) . w2 over this warp's 64 columns
    #pragma unroll
    for (int mi = 0; mi < 2; mi++) {
        #pragma unroll
        for (int rh = 0; rh < 2; rh++) {
            float part = 0.0f;
            #pragma unroll
            for (int ni = 0; ni < 8; ni++) {
                int col0 = warp_n * 64 + ni * 8 + 2 * (lane & 3);
                float h0 = acc[mi][ni][rh * 2 + 0] + s_b1[col0];
                float h1 = acc[mi][ni][rh * 2 + 1] + s_b1[col0 + 1];
                h0 = h0 > 0.f ? h0 : 0.f;
                h1 = h1 > 0.f ? h1 : 0.f;
                part = fmaf(h0, s_w2[col0], part);
                part = fmaf(h1, s_w2[col0 + 1], part);
            }
            part += __shfl_xor_sync(0xffffffffu, part, 1);
            part += __shfl_xor_sync(0xffffffffu, part, 2);
            if ((lane & 3) == 0)
                atomicAdd(&s_part[warp_m * 32 + mi * 16 + rh * 8 + (lane >> 2)], part);
        }
    }
    __syncthreads();
    if (tid < CTA_M) {
        float z = s_part[tid] + b2;
        s_alpha[tid] = 1.0f / (1.0f + expf(-z));
    }
    __syncthreads();

    // trivial epilogue: logits from g_hw + alpha store (l2 done in align)
    float* out_logits = out;
    float* out_alpha  = out + (size_t)ROWS * L;

    #pragma unroll
    for (int wi = 0; wi < 8; wi++) {
        int li = wid * 8 + wi;
        size_t row = (size_t)(r0 + li);
        float al = s_alpha[li];
        if (lane < L) {
            float hwh = g_hw[row * 16 + lane];
            float hwr = g_hw[row * 16 + 8 + lane];
            out_logits[row * L + lane] =
                fmaf(al, hwh, fmaf(1.0f - al, hwr, headb[lane]));
        }
        if (lane == 8)
            out_alpha[row] = al;
    }
}

extern "C" void kernel_launch(void* const* d_in, const int* in_sizes, int n_in,
                              void* d_out, int out_size)
{
    const float* hing = (const float*)d_in[0];
    const float* rob  = (const float*)d_in[1];
    const int*   hids = (const int*)d_in[2];
    const int*   rids = (const int*)d_in[3];
    // d_in[4] = num_words (unused by the reference outputs)
    const float* w1 = (const float*)d_in[5];
    const float* b1 = (const float*)d_in[6];
    const float* w2 = (const float*)d_in[7];
    const float* b2 = (const float*)d_in[8];
    const float* hw = (const float*)d_in[9];
    const float* hb = (const float*)d_in[10];
    float* out = (float*)d_out;

    cudaFuncSetAttribute(router_kernel,
                         cudaFuncAttributeMaxDynamicSharedMemorySize, SMEM_TOTAL);

    align_kernel<<<ALIGN_BLOCKS + (KX * H) / 256, 256>>>(
        hing, rob, hids, rids, w1, hw, out);
    router_kernel<<<ROWS / CTA_M, 256, SMEM_TOTAL>>>(b1, w2, b2, hb, out);
}